// round 16
// baseline (speedup 1.0000x reference)
#include <cuda_runtime.h>
#include <cstdint>

// FlowDE R16: R15 consolidated. A (x-side tf32 planes) staged ONCE for the
// full K=64 (removes the kk split: 2 fewer barriers, straight-line 8-ks QK
// mainloop -> ptxas can pipeline B-fragment LDGs across the whole loop).
// B operands (x0 QK tf32 frags, x0 PV bf16 frags) remain gmem fragment-ready.

#define Nn 4096
#define Mm 4096
#define Dd 64
#define Tt 8
#define Hh 0.125f
#define S0c 0.001f
#define MBLK 32
#define LDA 68   // u32 leading dim for A tf32 staging planes [128][68]

typedef unsigned long long u64;
typedef uint32_t u32;

__device__ __forceinline__ u32 to_tf32(float v) {
    u32 r; asm("cvt.rna.tf32.f32 %0, %1;" : "=r"(r) : "f"(v)); return r;
}
__device__ __forceinline__ void mma_tf32(float* d, const u32* a, const u32* b) {
    asm("mma.sync.aligned.m16n8k8.row.col.f32.tf32.tf32.f32 "
        "{%0,%1,%2,%3}, {%4,%5,%6,%7}, {%8,%9}, {%0,%1,%2,%3};"
        : "+f"(d[0]), "+f"(d[1]), "+f"(d[2]), "+f"(d[3])
        : "r"(a[0]), "r"(a[1]), "r"(a[2]), "r"(a[3]), "r"(b[0]), "r"(b[1]));
}
__device__ __forceinline__ void mma_bf16(float* d, const u32* a, u32 b0, u32 b1) {
    asm("mma.sync.aligned.m16n8k16.row.col.f32.bf16.bf16.f32 "
        "{%0,%1,%2,%3}, {%4,%5,%6,%7}, {%8,%9}, {%0,%1,%2,%3};"
        : "+f"(d[0]), "+f"(d[1]), "+f"(d[2]), "+f"(d[3])
        : "r"(a[0]), "r"(a[1]), "r"(a[2]), "r"(a[3]), "r"(b0), "r"(b1));
}
__device__ __forceinline__ u32 bf16pair(float v0, float v1) {
    u32 r; asm("cvt.rn.bf16x2.f32 %0, %1, %2;" : "=r"(r) : "f"(v1), "f"(v0));
    return r;
}
__device__ __forceinline__ float bf16lo_f(u32 p) { return __uint_as_float(p << 16); }
__device__ __forceinline__ float bf16hi_f(u32 p) {
    return __uint_as_float(p & 0xffff0000u);
}

// ---------------- globals -----------------------------------------------------
__device__ float g_xt[Nn * Dd];
__device__ float g_xeff[Nn * Dd];
__device__ float g_G1[Nn * Dd];
__device__ float g_x0sq[Mm];
__device__ float g_pmax[MBLK * Nn];
__device__ float g_psum[MBLK * Nn];
__device__ float g_qpart[(size_t)MBLK * Nn * Dd];
__device__ float g_xh32[Nn * Dd], g_xl32[Nn * Dd];     // tf32 split (QK A, per eval)
// x0 QK tf32 fragments: [mblk 32][gk 8][cblk 16][lane 32] uint4 {h@k, h@k+4, l@k, l@k+4}
__device__ u32 g_x0qku[32 * 8 * 16 * 32 * 4];          // 2 MB
// x0 PV bf16 fragments: [mblk 32][kgrp 8][dblk 8][lane 32] uint4 {ph@p, ph@p+4, pl@p, pl@p+4}
__device__ u32 g_x0pvu[32 * 8 * 8 * 32 * 4];           // 1 MB

__device__ __forceinline__ void split_tf32(float v, int idx, float* h, float* l) {
    u32 hb = to_tf32(v);
    float hf = __uint_as_float(hb);
    u32 lb = to_tf32(v - hf);
    h[idx] = hf;
    l[idx] = __uint_as_float(lb);
}

// ---------------------------------------------------------------------------
__global__ void k_init(const float* __restrict__ z, const float* __restrict__ x0) {
    int idx = blockIdx.x * blockDim.x + threadIdx.x;
    if (idx < Nn * Dd) {
        float v = z[idx];
        g_xt[idx] = v;
        g_xeff[idx] = v;
        split_tf32(v, idx, g_xh32, g_xl32);

        float w = x0[idx];
        u32 hb = to_tf32(w);
        u32 lb = to_tf32(w - __uint_as_float(hb));
        int m = idx >> 6, d = idx & 63;
        int mblk = m >> 7, mw = m & 127;
        int cblk = mw >> 3, gg = mw & 7;
        int gk = d >> 3, kr = d & 7;
        int tgx = kr & 3, hiq = kr >> 2;
        u32 base = ((((u32)mblk * 8 + gk) * 16 + cblk) * 32 + (gg * 4 + tgx)) * 4;
        g_x0qku[base + hiq] = hb;
        g_x0qku[base + 2 + hiq] = lb;
    }
    if (idx < Mm) {
        const float4* r = reinterpret_cast<const float4*>(x0 + idx * Dd);
        float s = 0.f;
#pragma unroll
        for (int i = 0; i < Dd / 4; i++) {
            float4 v = r[i];
            s += v.x * v.x + v.y * v.y + v.z * v.z + v.w * v.w;
        }
        g_x0sq[idx] = s;
    }
    if (idx < Dd * (Mm / 2)) {
        int d = idx >> 11;
        int mp = idx & 2047;
        float v0 = x0[(2 * mp) * Dd + d];
        float v1 = x0[(2 * mp + 1) * Dd + d];
        u32 ph = bf16pair(v0, v1);
        u32 pl = bf16pair(v0 - bf16lo_f(ph), v1 - bf16hi_f(ph));
        int mblk = mp >> 6, p = mp & 63;
        int kgrp = p >> 3, rem = p & 7;
        int tgx = rem & 3, hiq = rem >> 2;
        int dblk = d >> 3, gg = d & 7;
        u32 base = ((((u32)mblk * 8 + kgrp) * 8 + dblk) * 32 + (gg * 4 + tgx)) * 4;
        g_x0pvu[base + hiq] = ph;
        g_x0pvu[base + 2 + hiq] = pl;
    }
}

// ---------------------------------------------------------------------------
// SMEM map (dynamic, 73728 B):
//  [0,512)         x0sq
//  [1024,2048)     pm [128][2]
//  [2048,3072)     ps [128][2]
//  [4096,73728)    A tf32 planes Ah|Al [128][LDA]u32 each (69632)
//                  -> post-QK aliased by buf1 @4096 (34816), buf2 @38912 (34816)
// ---------------------------------------------------------------------------
extern __shared__ char dsm[];

__global__ __launch_bounds__(256, 2) void k_fused(float scale, float c2) {
    const int tid = threadIdx.x;
    const int n0 = blockIdx.y * 128;

    float* x0sq_s = reinterpret_cast<float*>(dsm);
    float* pm = reinterpret_cast<float*>(dsm + 1024);
    float* ps = reinterpret_cast<float*>(dsm + 2048);
    u32* Ah = reinterpret_cast<u32*>(dsm + 4096);
    u32* Al = Ah + 128 * LDA;
    float* buf1 = reinterpret_cast<float*>(dsm + 4096);    // alias post-QK
    float* buf2 = reinterpret_cast<float*>(dsm + 38912);   // alias post-QK

    const int wid = tid >> 5;
    const int lane = tid & 31;
    const int wr = wid >> 1;
    const int wc = wid & 1;
    const int g = lane >> 2;
    const int tg = lane & 3;

    if (tid < 128) x0sq_s[tid] = g_x0sq[blockIdx.x * 128 + tid];

    const uint4* QKB = reinterpret_cast<const uint4*>(g_x0qku) +
                       ((size_t)blockIdx.x * 8) * 16 * 32;
    const uint4* PVB = reinterpret_cast<const uint4*>(g_x0pvu) +
                       ((size_t)blockIdx.x * 8) * 8 * 32;

    // ---- stage full A (K=64) once ----
#pragma unroll
    for (int it = 0; it < 8; it++) {
        int idx = tid + 256 * it;            // 0..2047 float4 slots
        int row = idx >> 4, q = idx & 15;
        float4 vh = *reinterpret_cast<const float4*>(
            &g_xh32[(n0 + row) * Dd + 4 * q]);
        float4 vl = *reinterpret_cast<const float4*>(
            &g_xl32[(n0 + row) * Dd + 4 * q]);
        *reinterpret_cast<float4*>(&Ah[row * LDA + 4 * q]) = vh;
        *reinterpret_cast<float4*>(&Al[row * LDA + 4 * q]) = vl;
    }
    __syncthreads();

    float c[2][8][4];
#pragma unroll
    for (int rf = 0; rf < 2; rf++)
#pragma unroll
        for (int cm = 0; cm < 8; cm++)
#pragma unroll
            for (int e = 0; e < 4; e++) c[rf][cm][e] = 0.f;

    // ================= QK (tf32 3-product), straight-line 8 ks ==============
#pragma unroll
    for (int ks = 0; ks < 8; ks++) {
        int co = 8 * ks + tg;
        u32 ah[2][4], al[2][4];
#pragma unroll
        for (int rf = 0; rf < 2; rf++) {
            int rb = 32 * wr + 16 * rf;
            ah[rf][0] = Ah[(rb + g) * LDA + co];
            ah[rf][1] = Ah[(rb + g + 8) * LDA + co];
            ah[rf][2] = Ah[(rb + g) * LDA + co + 4];
            ah[rf][3] = Ah[(rb + g + 8) * LDA + co + 4];
            al[rf][0] = Al[(rb + g) * LDA + co];
            al[rf][1] = Al[(rb + g + 8) * LDA + co];
            al[rf][2] = Al[(rb + g) * LDA + co + 4];
            al[rf][3] = Al[(rb + g + 8) * LDA + co + 4];
        }
        const uint4* Bg = QKB + (ks * 16 + 8 * wc) * 32;
#pragma unroll
        for (int cm = 0; cm < 8; cm++) {
            uint4 bv = Bg[cm * 32 + lane];
            u32 bh[2] = {bv.x, bv.y};
            u32 bl[2] = {bv.z, bv.w};
#pragma unroll
            for (int rf = 0; rf < 2; rf++) {
                mma_tf32(c[rf][cm], ah[rf], bh);
                mma_tf32(c[rf][cm], ah[rf], bl);
                mma_tf32(c[rf][cm], al[rf], bh);
            }
        }
    }
    __syncthreads();   // A plane reads done -> buf1/buf2 alias writable later

    // ---- pass 1: bias in place, per-row(half) max ----
#pragma unroll
    for (int rf = 0; rf < 2; rf++) {
#pragma unroll
        for (int rh = 0; rh < 2; rh++) {
            float mx = -1e30f;
#pragma unroll
            for (int cm = 0; cm < 8; cm++) {
                int col = 64 * wc + 8 * cm + 2 * tg;
                float l0 = fmaf(scale, c[rf][cm][2 * rh], -c2 * x0sq_s[col]);
                float l1 = fmaf(scale, c[rf][cm][2 * rh + 1], -c2 * x0sq_s[col + 1]);
                c[rf][cm][2 * rh] = l0;
                c[rf][cm][2 * rh + 1] = l1;
                mx = fmaxf(mx, fmaxf(l0, l1));
            }
#pragma unroll
            for (int o = 1; o <= 2; o <<= 1)
                mx = fmaxf(mx, __shfl_xor_sync(0xffffffffu, mx, o));
            if (tg == 0) pm[(32 * wr + 16 * rf + 8 * rh + g) * 2 + wc] = mx;
        }
    }
    __syncthreads();

    // ---- pass 2: exp + bf16x2 split, all in registers; row sums ----
    u32 ph[2][8][2], pl[2][8][2];
#pragma unroll
    for (int rf = 0; rf < 2; rf++) {
#pragma unroll
        for (int rh = 0; rh < 2; rh++) {
            int row = 32 * wr + 16 * rf + 8 * rh + g;
            float M = fmaxf(pm[row * 2], pm[row * 2 + 1]);
            float sm = 0.f;
#pragma unroll
            for (int cm = 0; cm < 8; cm++) {
                float e0 = __expf(c[rf][cm][2 * rh] - M);
                float e1 = __expf(c[rf][cm][2 * rh + 1] - M);
                u32 hp = bf16pair(e0, e1);
                ph[rf][cm][rh] = hp;
                pl[rf][cm][rh] = bf16pair(e0 - bf16lo_f(hp), e1 - bf16hi_f(hp));
                sm += e0 + e1;
            }
#pragma unroll
            for (int o = 1; o <= 2; o <<= 1)
                sm += __shfl_xor_sync(0xffffffffu, sm, o);
            if (tg == 0) ps[row * 2 + wc] = sm;
        }
    }
    __syncthreads();

    if (tid < 128) {
        g_pmax[blockIdx.x * Nn + n0 + tid] = fmaxf(pm[tid * 2], pm[tid * 2 + 1]);
        g_psum[blockIdx.x * Nn + n0 + tid] = ps[tid * 2] + ps[tid * 2 + 1];
    }

    // ================= PV (bf16 3-product, A from regs, B from gmem frags) ===
    float* mybuf = wc ? buf2 : buf1;
#pragma unroll
    for (int dh = 0; dh < 2; dh++) {
        float cc[2][4][4];
#pragma unroll
        for (int rf = 0; rf < 2; rf++)
#pragma unroll
            for (int dcm = 0; dcm < 4; dcm++)
#pragma unroll
                for (int e = 0; e < 4; e++) cc[rf][dcm][e] = 0.f;

#pragma unroll
        for (int j = 0; j < 4; j++) {
            u32 a_h[2][4], a_l[2][4];
#pragma unroll
            for (int rf = 0; rf < 2; rf++) {
                a_h[rf][0] = ph[rf][2 * j][0];
                a_h[rf][1] = ph[rf][2 * j][1];
                a_h[rf][2] = ph[rf][2 * j + 1][0];
                a_h[rf][3] = ph[rf][2 * j + 1][1];
                a_l[rf][0] = pl[rf][2 * j][0];
                a_l[rf][1] = pl[rf][2 * j][1];
                a_l[rf][2] = pl[rf][2 * j + 1][0];
                a_l[rf][3] = pl[rf][2 * j + 1][1];
            }
            const uint4* Pg = PVB + ((wc * 4 + j) * 8) * 32;
#pragma unroll
            for (int dcm = 0; dcm < 4; dcm++) {
                uint4 bv = Pg[(4 * dh + dcm) * 32 + lane];
#pragma unroll
                for (int rf = 0; rf < 2; rf++) {
                    mma_bf16(cc[rf][dcm], a_h[rf], bv.x, bv.y);
                    mma_bf16(cc[rf][dcm], a_h[rf], bv.z, bv.w);
                    mma_bf16(cc[rf][dcm], a_l[rf], bv.x, bv.y);
                }
            }
        }

        // stash partials to this wc's buffer
#pragma unroll
        for (int rf = 0; rf < 2; rf++) {
#pragma unroll
            for (int dcm = 0; dcm < 4; dcm++) {
                int row = 32 * wr + 16 * rf + g;
                int col = 32 * dh + 8 * dcm + 2 * tg;
                *reinterpret_cast<float2*>(&mybuf[row * 68 + col]) =
                    make_float2(cc[rf][dcm][0], cc[rf][dcm][1]);
                *reinterpret_cast<float2*>(&mybuf[(row + 8) * 68 + col]) =
                    make_float2(cc[rf][dcm][2], cc[rf][dcm][3]);
            }
        }
    }
    __syncthreads();

    // cross-wc reduce + coalesced store of qpart slice
#pragma unroll
    for (int it = 0; it < 8; it++) {
        int lin = tid + 256 * it;            // 0..2047 float4 slots
        int row = lin >> 4, q4 = lin & 15;
        float4 v1 = *reinterpret_cast<const float4*>(&buf1[row * 68 + 4 * q4]);
        float4 v2 = *reinterpret_cast<const float4*>(&buf2[row * 68 + 4 * q4]);
        float4 s = make_float4(v1.x + v2.x, v1.y + v2.y, v1.z + v2.z, v1.w + v2.w);
        size_t off = (size_t)blockIdx.x * Nn * Dd + (size_t)(n0 + row) * Dd + 4 * q4;
        *reinterpret_cast<float4*>(&g_qpart[off]) = s;
    }
}

// ---------------------------------------------------------------------------
__global__ void k_update(float sigmat, int first, int last, float* __restrict__ out) {
    int i4 = blockIdx.x * blockDim.x + threadIdx.x;
    if (i4 >= Nn * Dd / 4) return;
    int n = i4 >> 4;

    float mx = -1e30f;
#pragma unroll
    for (int s = 0; s < MBLK; s++) mx = fmaxf(mx, g_pmax[s * Nn + n]);
    float rsum = 0.f;
    float4 q = make_float4(0.f, 0.f, 0.f, 0.f);
#pragma unroll
    for (int s = 0; s < MBLK; s++) {
        float ef = __expf(g_pmax[s * Nn + n] - mx);
        rsum = fmaf(g_psum[s * Nn + n], ef, rsum);
        float4 v = *reinterpret_cast<const float4*>(
            &g_qpart[(size_t)s * Nn * Dd + 4 * i4]);
        q.x = fmaf(v.x, ef, q.x);
        q.y = fmaf(v.y, ef, q.y);
        q.z = fmaf(v.z, ef, q.z);
        q.w = fmaf(v.w, ef, q.w);
    }
    float inv = 1.f / rsum;
    float4 xe = *reinterpret_cast<const float4*>(&g_xeff[4 * i4]);
    float4 xt = *reinterpret_cast<const float4*>(&g_xt[4 * i4]);
    float4 G1o = make_float4(0.f, 0.f, 0.f, 0.f);
    if (!first) G1o = *reinterpret_cast<const float4*>(&g_G1[4 * i4]);
    float4 G, xe2, xh, xl;
    float* Gp = &G.x; float* qp = &q.x; float* xep = &xe.x;
    float* xtp = &xt.x; float* xe2p = &xe2.x; float* xhp = &xh.x; float* xlp = &xl.x;
    float* G1p = &G1o.x;
#pragma unroll
    for (int e = 0; e < 4; e++) {
        float Gv = ((1.f - S0c) * xep[e] - qp[e] * inv) / sigmat;
        Gp[e] = Gv;
        if (!first) xtp[e] = xtp[e] - (G1p[e] + Gv) * (Hh * 0.5f);
        float x2 = xtp[e] - Hh * Gv;
        xe2p[e] = x2;
        u32 hb = to_tf32(x2);
        float hf = __uint_as_float(hb);
        xhp[e] = hf;
        xlp[e] = __uint_as_float(to_tf32(x2 - hf));
    }
    if (!first) *reinterpret_cast<float4*>(&g_xt[4 * i4]) = xt;
    *reinterpret_cast<float4*>(&g_G1[4 * i4]) = G;
    *reinterpret_cast<float4*>(&g_xeff[4 * i4]) = xe2;
    *reinterpret_cast<float4*>(&g_xh32[4 * i4]) = xh;
    *reinterpret_cast<float4*>(&g_xl32[4 * i4]) = xl;
    if (last) *reinterpret_cast<float4*>(&out[4 * i4]) = xt;
}

// ---------------------------------------------------------------------------
extern "C" void kernel_launch(void* const* d_in, const int* in_sizes, int n_in,
                              void* d_out, int out_size) {
    const float* z = (const float*)d_in[0];
    const float* x0 = (const float*)d_in[1];

    const int SMEM_F = 73728;
    cudaFuncSetAttribute(k_fused, cudaFuncAttributeMaxDynamicSharedMemorySize,
                         SMEM_F);

    k_init<<<(Nn * Dd + 255) / 256, 256>>>(z, x0);

    for (int e = 0; e < Tt; e++) {
        float t = (e == 0) ? 1.0f : (float)(Tt - e) / (float)Tt;
        float alphat = 1.0f - t;
        float sigmat = S0c + (1.0f - S0c) * t;
        float inv2s2 = 1.0f / (sigmat * sigmat);
        float scale = alphat * inv2s2;
        float c2 = 0.5f * alphat * alphat * inv2s2;

        k_fused<<<dim3(MBLK, 32), 256, SMEM_F>>>(scale, c2);
        k_update<<<(Nn * Dd / 4) / 256, 256>>>(sigmat, e == 0, e == Tt - 1,
                                               (float*)d_out);
    }
}

// round 17
// speedup vs baseline: 1.3109x; 1.3109x over previous
#include <cuda_runtime.h>
#include <cuda_fp16.h>
#include <cstdint>

// FlowDE R17: QK switched from tf32x3 m16n8k8 to fp16x3 m16n8k16 — same
// split residual (2^-22) but K=16 per mma: QK tensor slots and fragment
// traffic halve. PV (bf16x3, register-resident P, gmem fragment-ready B)
// and the whole epilogue are unchanged from R15.

#define Nn 4096
#define Mm 4096
#define Dd 64
#define Tt 8
#define Hh 0.125f
#define S0c 0.001f
#define MBLK 32
#define SA 36   // u32 leading dim, A fp16-pair planes [128][32 pairs + pad]

typedef unsigned long long u64;
typedef uint32_t u32;
typedef unsigned short u16;

__device__ __forceinline__ u32 f16pair(float v0, float v1) {
    u32 r; asm("cvt.rn.f16x2.f32 %0, %1, %2;" : "=r"(r) : "f"(v1), "f"(v0));
    return r;
}
__device__ __forceinline__ void mma_f16(float* d, const u32* a, u32 b0, u32 b1) {
    asm("mma.sync.aligned.m16n8k16.row.col.f32.f16.f16.f32 "
        "{%0,%1,%2,%3}, {%4,%5,%6,%7}, {%8,%9}, {%0,%1,%2,%3};"
        : "+f"(d[0]), "+f"(d[1]), "+f"(d[2]), "+f"(d[3])
        : "r"(a[0]), "r"(a[1]), "r"(a[2]), "r"(a[3]), "r"(b0), "r"(b1));
}
__device__ __forceinline__ void mma_bf16(float* d, const u32* a, u32 b0, u32 b1) {
    asm("mma.sync.aligned.m16n8k16.row.col.f32.bf16.bf16.f32 "
        "{%0,%1,%2,%3}, {%4,%5,%6,%7}, {%8,%9}, {%0,%1,%2,%3};"
        : "+f"(d[0]), "+f"(d[1]), "+f"(d[2]), "+f"(d[3])
        : "r"(a[0]), "r"(a[1]), "r"(a[2]), "r"(a[3]), "r"(b0), "r"(b1));
}
__device__ __forceinline__ u32 bf16pair(float v0, float v1) {
    u32 r; asm("cvt.rn.bf16x2.f32 %0, %1, %2;" : "=r"(r) : "f"(v1), "f"(v0));
    return r;
}
__device__ __forceinline__ float bf16lo_f(u32 p) { return __uint_as_float(p << 16); }
__device__ __forceinline__ float bf16hi_f(u32 p) {
    return __uint_as_float(p & 0xffff0000u);
}

// ---------------- globals -----------------------------------------------------
__device__ float g_xt[Nn * Dd];
__device__ float g_xeff[Nn * Dd];
__device__ float g_G1[Nn * Dd];
__device__ float g_x0sq[Mm];
__device__ float g_pmax[MBLK * Nn];
__device__ float g_psum[MBLK * Nn];
__device__ float g_qpart[(size_t)MBLK * Nn * Dd];
// x fp16 split pairs along d: [Nn][32] u32 (h plane, l plane) — rebuilt per eval
__device__ u32 g_xfh[Nn * Dd / 2], g_xfl[Nn * Dd / 2];
// x0 QK fp16 fragments: [mblk 32][ks 4][cblk 16][lane 32] uint4 {bh0,bh1,bl0,bl1}
__device__ u32 g_x0qku[32 * 4 * 16 * 32 * 4];          // 1 MB
// x0 PV bf16 fragments: [mblk 32][kgrp 8][dblk 8][lane 32] uint4 {ph,ph+4,pl,pl+4}
__device__ u32 g_x0pvu[32 * 8 * 8 * 32 * 4];           // 1 MB

// ---------------------------------------------------------------------------
__global__ void k_init(const float* __restrict__ z, const float* __restrict__ x0) {
    int idx = blockIdx.x * blockDim.x + threadIdx.x;
    if (idx < Nn * Dd) {
        float v = z[idx];
        g_xt[idx] = v;
        g_xeff[idx] = v;
        // x fp16 split (per element u16 write)
        __half hh = __float2half_rn(v);
        float hf = __half2float(hh);
        __half hl = __float2half_rn(v - hf);
        reinterpret_cast<u16*>(g_xfh)[idx] = __half_as_ushort(hh);
        reinterpret_cast<u16*>(g_xfl)[idx] = __half_as_ushort(hl);

        // x0 QK fp16 fragment scatter (element (m,d))
        float w = x0[idx];
        __half wh = __float2half_rn(w);
        float whf = __half2float(wh);
        __half wl = __float2half_rn(w - whf);
        int m = idx >> 6, d = idx & 63;
        int mblk = m >> 7, mw = m & 127;
        int cblk = mw >> 3, gg = mw & 7;
        int p = d >> 1, pe = d & 1;
        int ks = p >> 3, rem = p & 7;
        int tgx = rem & 3, hiq = rem >> 2;
        u32 slot = ((((u32)mblk * 4 + ks) * 16 + cblk) * 32 + (gg * 4 + tgx)) * 4;
        u16* q16 = reinterpret_cast<u16*>(g_x0qku);
        q16[(slot + hiq) * 2 + pe] = __half_as_ushort(wh);
        q16[(slot + 2 + hiq) * 2 + pe] = __half_as_ushort(wl);
    }
    if (idx < Mm) {
        const float4* r = reinterpret_cast<const float4*>(x0 + idx * Dd);
        float s = 0.f;
#pragma unroll
        for (int i = 0; i < Dd / 4; i++) {
            float4 v = r[i];
            s += v.x * v.x + v.y * v.y + v.z * v.z + v.w * v.w;
        }
        g_x0sq[idx] = s;
    }
    if (idx < Dd * (Mm / 2)) {
        int d = idx >> 11;
        int mp = idx & 2047;
        float v0 = x0[(2 * mp) * Dd + d];
        float v1 = x0[(2 * mp + 1) * Dd + d];
        u32 ph = bf16pair(v0, v1);
        u32 pl = bf16pair(v0 - bf16lo_f(ph), v1 - bf16hi_f(ph));
        int mblk = mp >> 6, p = mp & 63;
        int kgrp = p >> 3, rem = p & 7;
        int tgx = rem & 3, hiq = rem >> 2;
        int dblk = d >> 3, gg = d & 7;
        u32 base = ((((u32)mblk * 8 + kgrp) * 8 + dblk) * 32 + (gg * 4 + tgx)) * 4;
        g_x0pvu[base + hiq] = ph;
        g_x0pvu[base + 2 + hiq] = pl;
    }
}

// ---------------------------------------------------------------------------
// SMEM map (dynamic, 73728 B):
//  [0,512)         x0sq
//  [1024,2048)     pm [128][2]
//  [2048,3072)     ps [128][2]
//  [4096,40960)    A fp16-pair planes Ahp|Alp [128][SA]u32 each (36864)
//                  -> post-QK aliased by buf1 @4096 (34816), buf2 @38912 (34816)
// ---------------------------------------------------------------------------
extern __shared__ char dsm[];

__global__ __launch_bounds__(256, 2) void k_fused(float scale, float c2) {
    const int tid = threadIdx.x;
    const int n0 = blockIdx.y * 128;

    float* x0sq_s = reinterpret_cast<float*>(dsm);
    float* pm = reinterpret_cast<float*>(dsm + 1024);
    float* ps = reinterpret_cast<float*>(dsm + 2048);
    u32* Ahp = reinterpret_cast<u32*>(dsm + 4096);
    u32* Alp = Ahp + 128 * SA;
    float* buf1 = reinterpret_cast<float*>(dsm + 4096);    // alias post-QK
    float* buf2 = reinterpret_cast<float*>(dsm + 38912);   // alias post-QK

    const int wid = tid >> 5;
    const int lane = tid & 31;
    const int wr = wid >> 1;
    const int wc = wid & 1;
    const int g = lane >> 2;
    const int tg = lane & 3;

    if (tid < 128) x0sq_s[tid] = g_x0sq[blockIdx.x * 128 + tid];

    const uint4* QKB = reinterpret_cast<const uint4*>(g_x0qku) +
                       ((size_t)blockIdx.x * 4) * 16 * 32;
    const uint4* PVB = reinterpret_cast<const uint4*>(g_x0pvu) +
                       ((size_t)blockIdx.x * 8) * 8 * 32;

    // ---- stage A fp16-pair planes (full K) ----
#pragma unroll
    for (int it = 0; it < 4; it++) {
        int idx = tid + 256 * it;            // 0..1023 uint4 slots per plane
        int row = idx >> 3, q = idx & 7;     // 8 uint4 (32 u16) per row... (64 u16)
        uint4 vh = reinterpret_cast<const uint4*>(g_xfh)[(n0 + row) * 8 + q];
        uint4 vl = reinterpret_cast<const uint4*>(g_xfl)[(n0 + row) * 8 + q];
        *reinterpret_cast<uint4*>(&Ahp[row * SA + 4 * q]) = vh;
        *reinterpret_cast<uint4*>(&Alp[row * SA + 4 * q]) = vl;
    }
    __syncthreads();

    float c[2][8][4];
#pragma unroll
    for (int rf = 0; rf < 2; rf++)
#pragma unroll
        for (int cm = 0; cm < 8; cm++)
#pragma unroll
            for (int e = 0; e < 4; e++) c[rf][cm][e] = 0.f;

    // ================= QK (fp16 3-product, m16n8k16, 4 ks) ==================
#pragma unroll
    for (int ks = 0; ks < 4; ks++) {
        int co = 8 * ks + tg;
        u32 ah[2][4], al[2][4];
#pragma unroll
        for (int rf = 0; rf < 2; rf++) {
            int rb = 32 * wr + 16 * rf;
            ah[rf][0] = Ahp[(rb + g) * SA + co];
            ah[rf][1] = Ahp[(rb + g + 8) * SA + co];
            ah[rf][2] = Ahp[(rb + g) * SA + co + 4];
            ah[rf][3] = Ahp[(rb + g + 8) * SA + co + 4];
            al[rf][0] = Alp[(rb + g) * SA + co];
            al[rf][1] = Alp[(rb + g + 8) * SA + co];
            al[rf][2] = Alp[(rb + g) * SA + co + 4];
            al[rf][3] = Alp[(rb + g + 8) * SA + co + 4];
        }
        const uint4* Bg = QKB + (ks * 16 + 8 * wc) * 32;
#pragma unroll
        for (int cm = 0; cm < 8; cm++) {
            uint4 bv = Bg[cm * 32 + lane];
#pragma unroll
            for (int rf = 0; rf < 2; rf++) {
                mma_f16(c[rf][cm], ah[rf], bv.x, bv.y);
                mma_f16(c[rf][cm], ah[rf], bv.z, bv.w);
                mma_f16(c[rf][cm], al[rf], bv.x, bv.y);
            }
        }
    }
    __syncthreads();   // A plane reads done -> buf1/buf2 alias writable later

    // ---- pass 1: bias in place, per-row(half) max ----
#pragma unroll
    for (int rf = 0; rf < 2; rf++) {
#pragma unroll
        for (int rh = 0; rh < 2; rh++) {
            float mx = -1e30f;
#pragma unroll
            for (int cm = 0; cm < 8; cm++) {
                int col = 64 * wc + 8 * cm + 2 * tg;
                float l0 = fmaf(scale, c[rf][cm][2 * rh], -c2 * x0sq_s[col]);
                float l1 = fmaf(scale, c[rf][cm][2 * rh + 1], -c2 * x0sq_s[col + 1]);
                c[rf][cm][2 * rh] = l0;
                c[rf][cm][2 * rh + 1] = l1;
                mx = fmaxf(mx, fmaxf(l0, l1));
            }
#pragma unroll
            for (int o = 1; o <= 2; o <<= 1)
                mx = fmaxf(mx, __shfl_xor_sync(0xffffffffu, mx, o));
            if (tg == 0) pm[(32 * wr + 16 * rf + 8 * rh + g) * 2 + wc] = mx;
        }
    }
    __syncthreads();

    // ---- pass 2: exp + bf16x2 split, all in registers; row sums ----
    u32 ph[2][8][2], pl[2][8][2];
#pragma unroll
    for (int rf = 0; rf < 2; rf++) {
#pragma unroll
        for (int rh = 0; rh < 2; rh++) {
            int row = 32 * wr + 16 * rf + 8 * rh + g;
            float M = fmaxf(pm[row * 2], pm[row * 2 + 1]);
            float sm = 0.f;
#pragma unroll
            for (int cm = 0; cm < 8; cm++) {
                float e0 = __expf(c[rf][cm][2 * rh] - M);
                float e1 = __expf(c[rf][cm][2 * rh + 1] - M);
                u32 hp = bf16pair(e0, e1);
                ph[rf][cm][rh] = hp;
                pl[rf][cm][rh] = bf16pair(e0 - bf16lo_f(hp), e1 - bf16hi_f(hp));
                sm += e0 + e1;
            }
#pragma unroll
            for (int o = 1; o <= 2; o <<= 1)
                sm += __shfl_xor_sync(0xffffffffu, sm, o);
            if (tg == 0) ps[row * 2 + wc] = sm;
        }
    }
    __syncthreads();

    if (tid < 128) {
        g_pmax[blockIdx.x * Nn + n0 + tid] = fmaxf(pm[tid * 2], pm[tid * 2 + 1]);
        g_psum[blockIdx.x * Nn + n0 + tid] = ps[tid * 2] + ps[tid * 2 + 1];
    }

    // ================= PV (bf16 3-product, A from regs, B from gmem frags) ===
    float* mybuf = wc ? buf2 : buf1;
#pragma unroll
    for (int dh = 0; dh < 2; dh++) {
        float cc[2][4][4];
#pragma unroll
        for (int rf = 0; rf < 2; rf++)
#pragma unroll
            for (int dcm = 0; dcm < 4; dcm++)
#pragma unroll
                for (int e = 0; e < 4; e++) cc[rf][dcm][e] = 0.f;

#pragma unroll
        for (int j = 0; j < 4; j++) {
            u32 a_h[2][4], a_l[2][4];
#pragma unroll
            for (int rf = 0; rf < 2; rf++) {
                a_h[rf][0] = ph[rf][2 * j][0];
                a_h[rf][1] = ph[rf][2 * j][1];
                a_h[rf][2] = ph[rf][2 * j + 1][0];
                a_h[rf][3] = ph[rf][2 * j + 1][1];
                a_l[rf][0] = pl[rf][2 * j][0];
                a_l[rf][1] = pl[rf][2 * j][1];
                a_l[rf][2] = pl[rf][2 * j + 1][0];
                a_l[rf][3] = pl[rf][2 * j + 1][1];
            }
            const uint4* Pg = PVB + ((wc * 4 + j) * 8) * 32;
#pragma unroll
            for (int dcm = 0; dcm < 4; dcm++) {
                uint4 bv = Pg[(4 * dh + dcm) * 32 + lane];
#pragma unroll
                for (int rf = 0; rf < 2; rf++) {
                    mma_bf16(cc[rf][dcm], a_h[rf], bv.x, bv.y);
                    mma_bf16(cc[rf][dcm], a_h[rf], bv.z, bv.w);
                    mma_bf16(cc[rf][dcm], a_l[rf], bv.x, bv.y);
                }
            }
        }

        // stash partials to this wc's buffer
#pragma unroll
        for (int rf = 0; rf < 2; rf++) {
#pragma unroll
            for (int dcm = 0; dcm < 4; dcm++) {
                int row = 32 * wr + 16 * rf + g;
                int col = 32 * dh + 8 * dcm + 2 * tg;
                *reinterpret_cast<float2*>(&mybuf[row * 68 + col]) =
                    make_float2(cc[rf][dcm][0], cc[rf][dcm][1]);
                *reinterpret_cast<float2*>(&mybuf[(row + 8) * 68 + col]) =
                    make_float2(cc[rf][dcm][2], cc[rf][dcm][3]);
            }
        }
    }
    __syncthreads();

    // cross-wc reduce + coalesced store of qpart slice
#pragma unroll
    for (int it = 0; it < 8; it++) {
        int lin = tid + 256 * it;            // 0..2047 float4 slots
        int row = lin >> 4, q4 = lin & 15;
        float4 v1 = *reinterpret_cast<const float4*>(&buf1[row * 68 + 4 * q4]);
        float4 v2 = *reinterpret_cast<const float4*>(&buf2[row * 68 + 4 * q4]);
        float4 s = make_float4(v1.x + v2.x, v1.y + v2.y, v1.z + v2.z, v1.w + v2.w);
        size_t off = (size_t)blockIdx.x * Nn * Dd + (size_t)(n0 + row) * Dd + 4 * q4;
        *reinterpret_cast<float4*>(&g_qpart[off]) = s;
    }
}

// ---------------------------------------------------------------------------
__global__ void k_update(float sigmat, int first, int last, float* __restrict__ out) {
    int i4 = blockIdx.x * blockDim.x + threadIdx.x;
    if (i4 >= Nn * Dd / 4) return;
    int n = i4 >> 4;

    float mx = -1e30f;
#pragma unroll
    for (int s = 0; s < MBLK; s++) mx = fmaxf(mx, g_pmax[s * Nn + n]);
    float rsum = 0.f;
    float4 q = make_float4(0.f, 0.f, 0.f, 0.f);
#pragma unroll
    for (int s = 0; s < MBLK; s++) {
        float ef = __expf(g_pmax[s * Nn + n] - mx);
        rsum = fmaf(g_psum[s * Nn + n], ef, rsum);
        float4 v = *reinterpret_cast<const float4*>(
            &g_qpart[(size_t)s * Nn * Dd + 4 * i4]);
        q.x = fmaf(v.x, ef, q.x);
        q.y = fmaf(v.y, ef, q.y);
        q.z = fmaf(v.z, ef, q.z);
        q.w = fmaf(v.w, ef, q.w);
    }
    float inv = 1.f / rsum;
    float4 xe = *reinterpret_cast<const float4*>(&g_xeff[4 * i4]);
    float4 xt = *reinterpret_cast<const float4*>(&g_xt[4 * i4]);
    float4 G1o = make_float4(0.f, 0.f, 0.f, 0.f);
    if (!first) G1o = *reinterpret_cast<const float4*>(&g_G1[4 * i4]);
    float4 G, xe2;
    float x2a[4];
    float* Gp = &G.x; float* qp = &q.x; float* xep = &xe.x;
    float* xtp = &xt.x; float* xe2p = &xe2.x;
    float* G1p = &G1o.x;
#pragma unroll
    for (int e = 0; e < 4; e++) {
        float Gv = ((1.f - S0c) * xep[e] - qp[e] * inv) / sigmat;
        Gp[e] = Gv;
        if (!first) xtp[e] = xtp[e] - (G1p[e] + Gv) * (Hh * 0.5f);
        float x2 = xtp[e] - Hh * Gv;
        xe2p[e] = x2;
        x2a[e] = x2;
    }
    // fp16 split pairs (d 4-aligned -> pair-aligned)
    u32 hp0 = f16pair(x2a[0], x2a[1]);
    u32 hp1 = f16pair(x2a[2], x2a[3]);
    float h0 = __half2float(__ushort_as_half((u16)(hp0 & 0xffff)));
    float h1 = __half2float(__ushort_as_half((u16)(hp0 >> 16)));
    float h2 = __half2float(__ushort_as_half((u16)(hp1 & 0xffff)));
    float h3 = __half2float(__ushort_as_half((u16)(hp1 >> 16)));
    u32 lp0 = f16pair(x2a[0] - h0, x2a[1] - h1);
    u32 lp1 = f16pair(x2a[2] - h2, x2a[3] - h3);
    reinterpret_cast<uint2*>(g_xfh)[i4] = make_uint2(hp0, hp1);
    reinterpret_cast<uint2*>(g_xfl)[i4] = make_uint2(lp0, lp1);

    if (!first) *reinterpret_cast<float4*>(&g_xt[4 * i4]) = xt;
    *reinterpret_cast<float4*>(&g_G1[4 * i4]) = G;
    *reinterpret_cast<float4*>(&g_xeff[4 * i4]) = xe2;
    if (last) *reinterpret_cast<float4*>(&out[4 * i4]) = xt;
}

// ---------------------------------------------------------------------------
extern "C" void kernel_launch(void* const* d_in, const int* in_sizes, int n_in,
                              void* d_out, int out_size) {
    const float* z = (const float*)d_in[0];
    const float* x0 = (const float*)d_in[1];

    const int SMEM_F = 73728;
    cudaFuncSetAttribute(k_fused, cudaFuncAttributeMaxDynamicSharedMemorySize,
                         SMEM_F);

    k_init<<<(Nn * Dd + 255) / 256, 256>>>(z, x0);

    for (int e = 0; e < Tt; e++) {
        float t = (e == 0) ? 1.0f : (float)(Tt - e) / (float)Tt;
        float alphat = 1.0f - t;
        float sigmat = S0c + (1.0f - S0c) * t;
        float inv2s2 = 1.0f / (sigmat * sigmat);
        float scale = alphat * inv2s2;
        float c2 = 0.5f * alphat * alphat * inv2s2;

        k_fused<<<dim3(MBLK, 32), 256, SMEM_F>>>(scale, c2);
        k_update<<<(Nn * Dd / 4) / 256, 256>>>(sigmat, e == 0, e == Tt - 1,
                                               (float*)d_out);
    }
}